// round 1
// baseline (speedup 1.0000x reference)
#include <cuda_runtime.h>
#include <cstdint>
#include <cstddef>

#define DM 63
#define DD 64
#define NR_MAX 256
#define B_MAX 2048
#define TMAIN 128

// ---- scratch (static __device__ globals; no runtime allocation) ----
__device__ float g_Wt[2][(size_t)NR_MAX * DM * DD];   // transposed W, padded: [side][r][c][e], e=0 -> 0
__device__ float g_off[2][NR_MAX * DD];               // mobius offset per relation
__device__ float g_off2[2][NR_MAX];                   // sum(off^2)
__device__ float g_th[B_MAX * DD];                    // transformed head per batch row
__device__ float g_thb[B_MAX];                        // tanh(bias_head[u])

__device__ __forceinline__ float gelu_exact(float x) {
    return 0.5f * x * (1.0f + erff(x * 0.70710678118654752f));
}

// block reduction over 64 threads (2 warps)
__device__ __forceinline__ float bred64(float v, volatile float* wsum, int lane, int wid) {
    #pragma unroll
    for (int o = 16; o; o >>= 1) v += __shfl_down_sync(0xffffffffu, v, o);
    if (lane == 0) wsum[wid] = v;
    __syncthreads();
    float r = wsum[0] + wsum[1];
    __syncthreads();
    return r;
}

// ============================================================================
// K1: per-relation precompute. grid (NR, 2), block 64.
//   - product of 63 Householder reflections via rank-1 updates (O(Dm^2) each)
//   - stores W transposed + padded (col e=0 zero, flip applied to last column)
//   - mobius offset vector + its squared norm
// ============================================================================
__global__ void k_rel(const float* __restrict__ Wh,  const float* __restrict__ Wtt,
                      const float* __restrict__ rch, const float* __restrict__ dirh,
                      const float* __restrict__ rct, const float* __restrict__ dirt,
                      const float* __restrict__ fsh, const float* __restrict__ fst)
{
    int r    = blockIdx.x;
    int side = blockIdx.y;
    const float* Wemb = side ? Wtt  : Wh;
    const float* rc   = side ? rct  : rch;
    const float* dw   = side ? dirt : dirh;
    float fs          = side ? fst[0] : fsh[0];

    __shared__ float ws[DD];
    __shared__ float wsum[2];

    int tid = threadIdx.x;
    int lane = tid & 31, wid = tid >> 5;

    // thread i (< DM) owns row i of the running product P (registers, const-indexed)
    float prow[DM];
    #pragma unroll
    for (int k = 0; k < DM; k++) prow[k] = (k == tid) ? 1.0f : 0.0f;

    const float* wbase = Wemb + (size_t)r * DM * DM;
    for (int j = 0; j < DM; j++) {
        float wv = 0.0f;
        if (tid < DM) wv = gelu_exact(wbase[j * DM + tid]);
        ws[tid] = wv;
        float sq = wv * wv;
        #pragma unroll
        for (int o = 16; o; o >>= 1) sq += __shfl_down_sync(0xffffffffu, sq, o);
        if (lane == 0) wsum[wid] = sq;
        __syncthreads();
        float s2 = wsum[0] + wsum[1];
        // u_i = (P w)_i ; P_i -= (2 u_i / s2) * w
        float ui = 0.0f;
        #pragma unroll
        for (int k = 0; k < DM; k++) ui = fmaf(prow[k], ws[k], ui);
        float coef = 2.0f * ui / s2;
        #pragma unroll
        for (int k = 0; k < DM; k++) prow[k] = fmaf(-coef, ws[k], prow[k]);
        __syncthreads();
    }

    // store transposed+padded: g_Wt[side][r][c][1+i] = P[i][c] (last column flipped)
    float* base = &g_Wt[side][(size_t)r * DM * DD];
    if (tid < DM) {
        #pragma unroll
        for (int c = 0; c < DM; c++) {
            float v = prow[c];
            if (c == DM - 1) v *= fs;
            base[(size_t)c * DD + 1 + tid] = v;
        }
    } else { // tid == 63: zero the e=0 lane
        for (int c = 0; c < DM; c++) base[(size_t)c * DD] = 0.0f;
    }

    // ---- offset = expmap(c, 0.1 * normalize(d + <c,d> c)) ----
    float cv = rc[r * DD + tid];
    float dv = dw[r * DD + tid];
    float inner = bred64(cv * dv, wsum, lane, wid);
    float tv = fmaf(inner, cv, dv);
    float tn2 = bred64(tv * tv, wsum, lane, wid);
    tv = tv / (sqrtf(tn2) + 1e-6f);
    float uv = 0.1f * tv;
    float su2 = bred64(uv * uv, wsum, lane, wid);
    ws[tid] = uv;
    __syncthreads();
    float u0 = ws[0];
    float lin = su2 - 2.0f * u0 * u0;               // Minkowski inner
    float nrm = fminf(sqrtf(fmaxf(lin, 1e-8f)), 2.5f);
    float off = coshf(nrm) * cv + sinhf(nrm) * uv / nrm;
    g_off[side][r * DD + tid] = off;
    float off2 = bred64(off * off, wsum, lane, wid);
    if (tid == 0) g_off2[side][r] = off2;
}

// ============================================================================
// K2: head transform. grid B, block 64.
//   th[b] = mobius_add( flg(ent[u], Wr_h), offset_h[r] ); also tanh(bias_head)
// ============================================================================
__global__ void k_th(const float* __restrict__ ent, const float* __restrict__ bias_head,
                     const int* __restrict__ u_idx, const int* __restrict__ r_idx)
{
    int b = blockIdx.x;
    int tid = threadIdx.x;
    int lane = tid & 31, wid = tid >> 5;
    __shared__ float xs[DD];
    __shared__ float wsum[2];
    int u = u_idx[b];
    int r = r_idx[b];
    xs[tid] = ent[(size_t)u * DD + tid];
    __syncthreads();
    float yv;
    if (tid == 0) {
        yv = xs[0];
    } else {
        const float* wrow = &g_Wt[0][((size_t)r * DM + (tid - 1)) * DD];
        float a0 = 0, a1 = 0, a2 = 0, a3 = 0;
        #pragma unroll
        for (int e = 0; e < DD; e += 4) {
            a0 = fmaf(xs[e    ], wrow[e    ], a0);
            a1 = fmaf(xs[e + 1], wrow[e + 1], a1);
            a2 = fmaf(xs[e + 2], wrow[e + 2], a2);
            a3 = fmaf(xs[e + 3], wrow[e + 3], a3);
        }
        yv = (a0 + a1) + (a2 + a3);
    }
    float offv = g_off[0][r * DD + tid];
    float x2 = bred64(yv * yv, wsum, lane, wid);
    float xy = bred64(yv * offv, wsum, lane, wid);
    float y2 = g_off2[0][r];
    float A   = 1.0f + 2.0f * xy + y2;
    float Bc  = 1.0f - x2;
    float den = 1.0f + 2.0f * xy + x2 * y2 + 1e-15f;
    g_th[b * DD + tid] = fmaf(A, yv, Bc * offv) / den;
    if (tid == 0) g_thb[b] = tanhf(bias_head[u]);
}

// ============================================================================
// K3: main scoring kernel. grid B, block 128, 4 tails/thread.
//   y = x @ Wr_t (W^T in smem, x in regs), fused mobius + Minkowski score.
// ============================================================================
__global__ void __launch_bounds__(TMAIN) k_main(
    const float* __restrict__ ent, const float* __restrict__ bias_tail,
    const int* __restrict__ r_idx, const int* __restrict__ v_idx,
    float* __restrict__ out, int N)
{
    __shared__ __align__(16) float Wt_s[DM * DD];   // 16128 B
    __shared__ float th_s[DD];
    __shared__ float off_s[DD];
    __shared__ float ys[DM * TMAIN];                // 32256 B (spatial y staging)

    int b = blockIdx.x;
    int tid = threadIdx.x;
    int r = r_idx[b];

    {
        const float4* src = (const float4*)&g_Wt[1][(size_t)r * DM * DD];
        float4* dst = (float4*)Wt_s;
        #pragma unroll 4
        for (int i = tid; i < DM * DD / 4; i += TMAIN) dst[i] = src[i];
    }
    if (tid < DD) {
        th_s[tid]  = g_th[b * DD + tid];
        off_s[tid] = g_off[1][r * DD + tid];
    }
    float off2 = g_off2[1][r];
    float thb  = g_thb[b];
    __syncthreads();

    for (int n = tid; n < N; n += TMAIN) {
        int v = v_idx[b * N + n];
        const float4* xr = (const float4*)(ent + (size_t)v * DD);
        float4 xq[16];
        #pragma unroll
        for (int q = 0; q < 16; q++) xq[q] = xr[q];

        float y0v = xq[0].x;
        float x2a = y0v * y0v;
        float xya = y0v * off_s[0];

        const float4* W4 = (const float4*)Wt_s;
        #pragma unroll 3
        for (int c = 0; c < DM; c++) {
            const float4* wr = W4 + c * 16;
            float a0 = 0, a1 = 0, a2 = 0, a3 = 0;
            #pragma unroll
            for (int q = 0; q < 16; q++) {
                float4 w = wr[q];                       // broadcast LDS.128
                a0 = fmaf(xq[q].x, w.x, a0);
                a1 = fmaf(xq[q].y, w.y, a1);
                a2 = fmaf(xq[q].z, w.z, a2);
                a3 = fmaf(xq[q].w, w.w, a3);
            }
            float acc = (a0 + a1) + (a2 + a3);
            x2a = fmaf(acc, acc, x2a);
            xya = fmaf(acc, off_s[c + 1], xya);
            ys[c * TMAIN + tid] = acc;
        }

        float A    = 1.0f + 2.0f * xya + off2;
        float Bc   = 1.0f - x2a;
        float den  = 1.0f + 2.0f * xya + x2a * off2 + 1e-15f;
        float rden = 1.0f / den;

        float d0 = fmaf(A, y0v, Bc * off_s[0]) * rden - th_s[0];
        float mkv = -(d0 * d0);                          // running: sum d^2 - 2 d0^2
        #pragma unroll 7
        for (int c = 1; c < DD; c++) {
            float yv = ys[(c - 1) * TMAIN + tid];
            float dd = fmaf(A, yv, Bc * off_s[c]) * rden - th_s[c];
            mkv = fmaf(dd, dd, mkv);
        }

        float btv = tanhf(bias_tail[v]);
        out[(size_t)b * N + n] = 8.0f - mkv + thb + btv;
    }
}

// ============================================================================
extern "C" void kernel_launch(void* const* d_in, const int* in_sizes, int n_in,
                              void* d_out, int out_size)
{
    (void)n_in; (void)out_size;
    const float* ent  = (const float*)d_in[0];
    const float* Wh   = (const float*)d_in[1];
    const float* Wtt  = (const float*)d_in[2];
    const float* rch  = (const float*)d_in[3];
    const float* dirh = (const float*)d_in[4];
    const float* rct  = (const float*)d_in[5];
    const float* dirt = (const float*)d_in[6];
    const float* bh   = (const float*)d_in[7];
    const float* bt   = (const float*)d_in[8];
    const float* fsh  = (const float*)d_in[9];
    const float* fst  = (const float*)d_in[10];
    const int* u_idx  = (const int*)d_in[11];
    const int* r_idx  = (const int*)d_in[12];
    const int* v_idx  = (const int*)d_in[13];
    float* out = (float*)d_out;

    int NR = in_sizes[3] / DD;       // 237
    int B  = in_sizes[11];           // 1024
    int N  = in_sizes[13] / B;       // 512

    k_rel<<<dim3(NR, 2), 64>>>(Wh, Wtt, rch, dirh, rct, dirt, fsh, fst);
    k_th<<<B, 64>>>(ent, bh, u_idx, r_idx);
    k_main<<<B, TMAIN>>>(ent, bt, r_idx, v_idx, out, N);
}